// round 16
// baseline (speedup 1.0000x reference)
#include <cuda_runtime.h>
#include <math.h>

#define Bsz 8
#define Esz 2000
#define Nsz 10000
#define NRELc 25
#define Ksz 16
#define Tsz 3
#define Lsz 32
#define TAU1f 10.0f
#define BL 256
#define COL4 64
#define TPB 8
#define SLOTS 32
#define BMW 64
#define PGRID (Esz / TPB)    // 250 blocks

// ---------------- scratch ----------------
__device__ int      g_heads[Nsz];
__device__ int      g_rels[Nsz];
__device__ int      g_tailof[Nsz];
__device__ int      g_slotn[Esz * SLOTS];   // tail-keyed CSR slots
__device__ int      g_cnt[Esz];             // tail degree (zeroed in cleanup)
__device__ int      g_hslotn[Esz * SLOTS];  // head-keyed CSR slots
__device__ int      g_hcnt[Esz];            // head degree (zeroed in cleanup)
__device__ int      g_tidx[Esz];
__device__ int      g_ent[Bsz];
__device__ float    g_val[Bsz];
__device__ float    g_hx0g[BL];
__device__ float    g_wp[Tsz * NRELc * Lsz];
__device__ float    g_shp[Tsz * (NRELc - 1) * Lsz];
__device__ float    g_shtp[Tsz * Ksz * Lsz];
__device__ float    g_ab[Tsz * Lsz * 2];
__device__ float    g_tw[Lsz];
__device__ unsigned g_bm0[BMW];
__device__ unsigned g_bm1[BMW];
__device__ float    g_sA[Esz * BL];
__device__ float    g_sB[Esz * BL];
__device__ volatile unsigned g_front;        // frontier-done flag
__device__ volatile unsigned g_rdyA[BMW];    // sA row-ready bits
__device__ volatile unsigned g_rdyB[BMW];    // sB row-ready bits
__device__ unsigned g_fin;

__device__ __forceinline__ float clip01(float x) { return fminf(fmaxf(x, 0.0f), 1.0f); }

// ============ 1) streaming extraction + both CSRs + tables ============
__global__ void k_setup(const uint4* __restrict__ e2t,
                        const uint4* __restrict__ t2e,
                        const uint4* __restrict__ t2r,
                        const float* __restrict__ input_x,
                        const float* __restrict__ type_mat,
                        const float* __restrict__ alpha, const float* __restrict__ beta,
                        const float* __restrict__ w, const float* __restrict__ h,
                        const float* __restrict__ h_type, const float* __restrict__ weight) {
    const unsigned tid0 = threadIdx.x;
    const unsigned bi = blockIdx.x;
    const unsigned tid = bi * blockDim.x + tid0;
    const unsigned stride = gridDim.x * blockDim.x;

    // ---- tables (param-only; designated blocks) ----
    if (bi == 0) {
        if (tid0 < Tsz * Lsz) {
            int tt = tid0 / Lsz, l = tid0 % Lsz;
            const float* wr = w + (tt * Lsz + l) * NRELc;
            float m = -1e30f;
#pragma unroll
            for (int r = 0; r < NRELc; r++) m = fmaxf(m, wr[r]);
            float s = 0.0f, ev[NRELc];
#pragma unroll
            for (int r = 0; r < NRELc; r++) { ev[r] = expf(wr[r] - m); s += ev[r]; }
            float inv = 1.0f / s;
#pragma unroll
            for (int r = 0; r < NRELc; r++)
                g_wp[(tt * NRELc + r) * Lsz + l] = ev[r] * inv;
            g_ab[(tt * Lsz + l) * 2 + 0] = clip01(alpha[tt * Lsz + l] / TAU1f);
            g_ab[(tt * Lsz + l) * 2 + 1] = clip01(beta[tt * Lsz + l] / TAU1f);
        } else if (tid0 < Tsz * Lsz + Lsz) {
            int l = tid0 - Tsz * Lsz;
            g_tw[l] = tanhf(weight[l]);
        }
    }
    if (bi >= 1 && bi < 10) {
        int i = (int)(bi - 1) * 256 + (int)tid0;
        if (i < Tsz * (NRELc - 1) * Lsz) {
            int tt = i / ((NRELc - 1) * Lsz);
            int rem = i % ((NRELc - 1) * Lsz);
            int j = rem / Lsz, l = rem % Lsz;
            g_shp[i] = clip01(h[(tt * Lsz + l) * (NRELc - 1) + j] / TAU1f);
        }
    }
    if (bi >= 10 && bi < 16) {
        int i = (int)(bi - 10) * 256 + (int)tid0;
        if (i < Tsz * Ksz * Lsz) {
            int tt = i / (Ksz * Lsz);
            int rem = i % (Ksz * Lsz);
            int k = rem / Lsz, l = rem % Lsz;
            g_shtp[i] = clip01(h_type[(tt * Lsz + l) * Ksz + k] / TAU1f);
        }
    }

    for (unsigned i = tid; i < Bsz * Esz; i += stride) {
        float v = input_x[i];
        if (v != 0.0f) { g_ent[i / Esz] = (int)(i % Esz); g_val[i / Esz] = v; }
    }
    for (unsigned i = tid; i < Esz * Ksz; i += stride)
        if (type_mat[i] != 0.0f) g_tidx[i / Ksz] = (int)(i % Ksz);

    const unsigned n3 = Nsz * NRELc / 4;
    for (unsigned i = tid; i < n3; i += stride) {
        uint4 v = __ldcs(&t2r[i]);
        if (v.x | v.y | v.z | v.w) {
            unsigned base = i * 4u;
            if (v.x) { unsigned id = base + 0; g_rels[id / NRELc] = (int)(id % NRELc); }
            if (v.y) { unsigned id = base + 1; g_rels[id / NRELc] = (int)(id % NRELc); }
            if (v.z) { unsigned id = base + 2; g_rels[id / NRELc] = (int)(id % NRELc); }
            if (v.w) { unsigned id = base + 3; g_rels[id / NRELc] = (int)(id % NRELc); }
        }
    }

    // e2triple [E,N] -> heads + head-keyed slots
    const unsigned n1 = (unsigned)Esz * Nsz / 4;
    {
        unsigned i = tid;
        for (; i + 3 * stride < n1; i += 4 * stride) {
            uint4 a0 = __ldcs(&e2t[i]);
            uint4 a1 = __ldcs(&e2t[i + stride]);
            uint4 a2 = __ldcs(&e2t[i + 2 * stride]);
            uint4 a3 = __ldcs(&e2t[i + 3 * stride]);
#define PROC_H(vv, ii) \
            if ((vv).x | (vv).y | (vv).z | (vv).w) { \
                unsigned base = (ii) * 4u; \
                unsigned wsv[4] = {(vv).x, (vv).y, (vv).z, (vv).w}; \
                _Pragma("unroll") \
                for (int k = 0; k < 4; k++) if (wsv[k]) { \
                    unsigned id = base + k; \
                    unsigned n = id % Nsz; int e = (int)(id / Nsz); \
                    g_heads[n] = e; \
                    int s = atomicAdd(&g_hcnt[e], 1); \
                    if (s < SLOTS) g_hslotn[e * SLOTS + s] = (int)n; } }
            PROC_H(a0, i) PROC_H(a1, i + stride) PROC_H(a2, i + 2 * stride) PROC_H(a3, i + 3 * stride)
        }
        for (; i < n1; i += stride) { uint4 a = __ldcs(&e2t[i]); PROC_H(a, i) }
    }
    // triple2e [N,E] -> tail-keyed slots + tailof
    const unsigned n2 = (unsigned)Nsz * Esz / 4;
    {
        unsigned i = tid;
        for (; i + 3 * stride < n2; i += 4 * stride) {
            uint4 a0 = __ldcs(&t2e[i]);
            uint4 a1 = __ldcs(&t2e[i + stride]);
            uint4 a2 = __ldcs(&t2e[i + 2 * stride]);
            uint4 a3 = __ldcs(&t2e[i + 3 * stride]);
#define PROC_T(vv, ii) \
            if ((vv).x | (vv).y | (vv).z | (vv).w) { \
                unsigned base = (ii) * 4u; \
                unsigned wsv[4] = {(vv).x, (vv).y, (vv).z, (vv).w}; \
                _Pragma("unroll") \
                for (int k = 0; k < 4; k++) if (wsv[k]) { \
                    unsigned id = base + k; \
                    unsigned n = id / Esz, tl = id % Esz; \
                    g_tailof[n] = (int)tl; \
                    int slot = atomicAdd(&g_cnt[tl], 1); \
                    if (slot < SLOTS) g_slotn[tl * SLOTS + slot] = (int)n; } }
            PROC_T(a0, i) PROC_T(a1, i + stride) PROC_T(a2, i + 2 * stride) PROC_T(a3, i + 3 * stride)
        }
        for (; i < n2; i += stride) { uint4 a = __ldcs(&t2e[i]); PROC_T(a, i) }
    }
}

// ============ 2) fused dataflow kernel (no grid barriers) ============
__global__ void __launch_bounds__(256, 2)
k_fused(const float* __restrict__ alpha, const float* __restrict__ beta,
        const float* __restrict__ alpha_x, const float* __restrict__ beta_x,
        const float* __restrict__ h_x, const float* __restrict__ h_x_type,
        float* __restrict__ out) {
    const int tid = threadIdx.x;
    const int bi = blockIdx.x;
    const int g = tid >> 5;          // row 0..7 (one warp per row)
    const int c2 = tid & 31;         // lane; owns float4 slots {2c2, 2c2+1}
    const int ca = 2 * c2, cb = 2 * c2 + 1;
    const int b = c2 >> 2;
    const int e0 = bi * TPB;
    const int e  = e0 + g;

    __shared__ unsigned strip[TPB][SLOTS];
    __shared__ float    swp[Tsz * NRELc * Lsz];   // 9.6 KB
    __shared__ float    shid[Tsz][TPB][Lsz];      // 3 KB
    __shared__ unsigned smaskl[TPB];
    __shared__ int      scnt[TPB];
    __shared__ int      sent[Bsz];
    __shared__ float    sval[Bsz];
    __shared__ unsigned sbm0[BMW], sbm1[BMW];
    // frontier-only (block 0)
    __shared__ float    shxacc[Bsz * NRELc];
    __shared__ int      slist[256];
    __shared__ int      slcnt;

    if (tid < TPB) { smaskl[tid] = 0u; scnt[tid] = min(g_cnt[e0 + tid], SLOTS); }
    if (tid >= 32 && tid < 32 + Bsz) { sent[tid - 32] = g_ent[tid - 32]; sval[tid - 32] = g_val[tid - 32]; }
    for (int i = tid; i < Tsz * NRELc * Lsz; i += 256) swp[i] = g_wp[i];
    __syncthreads();

    // ---- stage A: strips + masks ----
    if (c2 < scnt[g]) {
        int n = g_slotn[e * SLOTS + c2];
        int hd = g_heads[n], r = g_rels[n];
        strip[g][c2] = (unsigned)hd | ((unsigned)r << 11);
        if (r < NRELc - 1) atomicOr(&smaskl[g], 1u << r);
    }
    __syncthreads();

    // ---- all 3 shid tables ----
    {
        int row = g, l = c2;
        int ti = g_tidx[e0 + row];
        unsigned mrow = smaskl[row];
#pragma unroll
        for (int t = 0; t < Tsz; t++) {
            float a  = g_ab[(t * Lsz + l) * 2 + 0];
            float bb = g_ab[(t * Lsz + l) * 2 + 1];
            float s1 = g_shtp[(t * Ksz + ti) * Lsz + l];
            float s2 = 0.0f;
            unsigned m = mrow;
            while (m) { int jj = __ffs(m) - 1; s2 += g_shp[(t * (NRELc - 1) + jj) * Lsz + l]; m &= m - 1; }
            shid[t][row][l] = clip01(a * s1 + bb * s2) + (1.0f - clip01(a + bb));
        }
    }

    // ---- frontier (block 0) / wait for frontier (others) ----
    if (bi == 0) {
        if (tid < Bsz * NRELc) shxacc[tid] = 0.0f;
        if (tid < BMW) { sbm0[tid] = 0u; sbm1[tid] = 0u; }
        if (tid == 0) slcnt = 0;
        __syncthreads();
        // hop 1: entities -> bm0 + hx accumulation
        {
            int b2 = g, slot = c2;
            int entb = sent[b2];
            int hc = min(g_hcnt[entb], SLOTS);
            if (slot < hc) {
                int n = g_hslotn[entb * SLOTS + slot];
                int tl = g_tailof[n], r = g_rels[n];
                atomicOr(&sbm0[tl >> 5], 1u << (tl & 31));
                atomicAdd(&shxacc[b2 * NRELc + r], sval[b2]);
            }
        }
        __syncthreads();
        // list of bm0 rows
        for (int i = tid; i < Esz; i += 256)
            if ((sbm0[i >> 5] >> (i & 31)) & 1u) { int p = atomicAdd(&slcnt, 1); slist[p] = i; }
        __syncthreads();
        // hop 2: bm0 rows -> bm1
        {
            int tot = slcnt * SLOTS;
            for (int i = tid; i < tot; i += 256) {
                int row = slist[i >> 5], slot = i & 31;
                int hc = min(g_hcnt[row], SLOTS);
                if (slot < hc) {
                    int n = g_hslotn[row * SLOTS + slot];
                    int tl = g_tailof[n];
                    atomicOr(&sbm1[tl >> 5], 1u << (tl & 31));
                }
            }
        }
        __syncthreads();
        // hx0 per (b,l)
        {
            int b2 = tid >> 5, l = tid & 31;
            int entb = sent[b2]; float valb = sval[b2];
            float a  = clip01(alpha[l] / TAU1f);
            float bb = clip01(beta[l] / TAU1f);
            float gate = 1.0f - clip01(clip01(alpha_x[l] / TAU1f) + clip01(beta_x[l] / TAU1f));
            float htx = clip01(h_x_type[l * Ksz + g_tidx[entb]] / TAU1f) * valb;
            float hxl = 0.0f;
#pragma unroll
            for (int j = 0; j < NRELc - 1; j++) {
                int col = (j < 12) ? (12 + j) : (j - 12);
                hxl += clip01(shxacc[b2 * NRELc + col]) * clip01(h_x[l * (NRELc - 1) + j] / TAU1f);
            }
            g_hx0g[tid] = clip01(a * htx + bb * hxl) + gate;
        }
        if (tid < BMW) { g_bm0[tid] = sbm0[tid]; g_bm1[tid] = sbm1[tid]; }
        __syncthreads();
        __threadfence();
        if (tid == 0) g_front = 1u;
    } else {
        if (tid == 0) {
            while (g_front == 0u) __nanosleep(32);
        }
        __syncthreads();
        __threadfence();
        if (tid < BMW) sbm0[tid] = g_bm0[tid];
        else if (tid < 2 * BMW) sbm1[tid - BMW] = g_bm1[tid - BMW];
        __syncthreads();
    }

    const bool act0 = (sbm0[e >> 5] >> (e & 31)) & 1u;
    const bool act1 = (sbm1[e >> 5] >> (e & 31)) & 1u;
    const float4* swp4 = (const float4*)swp;
    const int cnt = scnt[g];

    // ================= phase 0: input -> sA (bm0 rows) =================
    if (act0) {
        int sentb = sent[b]; float svalb = sval[b];
        float4 acca = make_float4(0.f, 0.f, 0.f, 0.f);
        float4 accb = make_float4(0.f, 0.f, 0.f, 0.f);
        for (int j = 0; j < cnt; j++) {
            unsigned u = strip[g][j];
            if ((int)(u & 0x7ffu) == sentb) {
                unsigned rbase = (0 * NRELc + (u >> 11)) * 8;
                float4 wa = swp4[rbase + (ca & 7)];
                float4 wb = swp4[rbase + (cb & 7)];
                acca.x = fmaf(svalb, wa.x, acca.x); acca.y = fmaf(svalb, wa.y, acca.y);
                acca.z = fmaf(svalb, wa.z, acca.z); acca.w = fmaf(svalb, wa.w, acca.w);
                accb.x = fmaf(svalb, wb.x, accb.x); accb.y = fmaf(svalb, wb.y, accb.y);
                accb.z = fmaf(svalb, wb.z, accb.z); accb.w = fmaf(svalb, wb.w, accb.w);
            }
        }
        float4 ha = ((const float4*)shid[0][g])[ca & 7];
        float4 hb = ((const float4*)shid[0][g])[cb & 7];
        float4 xa = __ldg(&((const float4*)g_hx0g)[ca]);
        float4 xb = __ldg(&((const float4*)g_hx0g)[cb]);
        ((float4*)g_sA)[e * COL4 + ca] = make_float4(
            acca.x * ha.x * xa.x, acca.y * ha.y * xa.y, acca.z * ha.z * xa.z, acca.w * ha.w * xa.w);
        ((float4*)g_sA)[e * COL4 + cb] = make_float4(
            accb.x * hb.x * xb.x, accb.y * hb.y * xb.y, accb.z * hb.z * xb.z, accb.w * hb.w * xb.w);
        __threadfence();
        __syncwarp();
        if (c2 == 0) atomicOr((unsigned*)&g_rdyA[e >> 5], 1u << (e & 31));
    }

    // ================= phase 1: sA -> sB (bm1 rows) =================
    if (act1) {
        for (int j = 0; j < cnt; j++) {
            unsigned head = strip[g][j] & 0x7ffu;
            if ((sbm0[head >> 5] >> (head & 31)) & 1u) {
                volatile unsigned* wptr = &g_rdyA[head >> 5];
                unsigned bit = head & 31;
                while (!((*wptr >> bit) & 1u)) __nanosleep(32);
            }
        }
        __threadfence();
        float4 acca = make_float4(0.f, 0.f, 0.f, 0.f);
        float4 accb = make_float4(0.f, 0.f, 0.f, 0.f);
        for (int j = 0; j < cnt; j++) {
            unsigned u = strip[g][j];
            unsigned head = u & 0x7ffu;
            if ((sbm0[head >> 5] >> (head & 31)) & 1u) {
                float4 va = ((const float4*)g_sA)[head * COL4 + ca];
                float4 vb = ((const float4*)g_sA)[head * COL4 + cb];
                unsigned rbase = (1 * NRELc + (u >> 11)) * 8;
                float4 wa = swp4[rbase + (ca & 7)];
                float4 wb = swp4[rbase + (cb & 7)];
                acca.x = fmaf(va.x, wa.x, acca.x); acca.y = fmaf(va.y, wa.y, acca.y);
                acca.z = fmaf(va.z, wa.z, acca.z); acca.w = fmaf(va.w, wa.w, acca.w);
                accb.x = fmaf(vb.x, wb.x, accb.x); accb.y = fmaf(vb.y, wb.y, accb.y);
                accb.z = fmaf(vb.z, wb.z, accb.z); accb.w = fmaf(vb.w, wb.w, accb.w);
            }
        }
        float4 ha = ((const float4*)shid[1][g])[ca & 7];
        float4 hb = ((const float4*)shid[1][g])[cb & 7];
        ((float4*)g_sB)[e * COL4 + ca] = make_float4(
            acca.x * ha.x, acca.y * ha.y, acca.z * ha.z, acca.w * ha.w);
        ((float4*)g_sB)[e * COL4 + cb] = make_float4(
            accb.x * hb.x, accb.y * hb.y, accb.z * hb.z, accb.w * hb.w);
        __threadfence();
        __syncwarp();
        if (c2 == 0) atomicOr((unsigned*)&g_rdyB[e >> 5], 1u << (e & 31));
    }

    // ================= phase 2: sB -> out (dense) =================
    {
        for (int j = 0; j < cnt; j++) {
            unsigned head = strip[g][j] & 0x7ffu;
            if ((sbm1[head >> 5] >> (head & 31)) & 1u) {
                volatile unsigned* wptr = &g_rdyB[head >> 5];
                unsigned bit = head & 31;
                while (!((*wptr >> bit) & 1u)) __nanosleep(32);
            }
        }
        __threadfence();
        float4 acca = make_float4(0.f, 0.f, 0.f, 0.f);
        float4 accb = make_float4(0.f, 0.f, 0.f, 0.f);
        for (int j = 0; j < cnt; j++) {
            unsigned u = strip[g][j];
            unsigned head = u & 0x7ffu;
            if ((sbm1[head >> 5] >> (head & 31)) & 1u) {
                float4 va = ((const float4*)g_sB)[head * COL4 + ca];
                float4 vb = ((const float4*)g_sB)[head * COL4 + cb];
                unsigned rbase = (2 * NRELc + (u >> 11)) * 8;
                float4 wa = swp4[rbase + (ca & 7)];
                float4 wb = swp4[rbase + (cb & 7)];
                acca.x = fmaf(va.x, wa.x, acca.x); acca.y = fmaf(va.y, wa.y, acca.y);
                acca.z = fmaf(va.z, wa.z, acca.z); acca.w = fmaf(va.w, wa.w, acca.w);
                accb.x = fmaf(vb.x, wb.x, accb.x); accb.y = fmaf(vb.y, wb.y, accb.y);
                accb.z = fmaf(vb.z, wb.z, accb.z); accb.w = fmaf(vb.w, wb.w, accb.w);
            }
        }
        float4 ha = ((const float4*)shid[2][g])[ca & 7];
        float4 hb = ((const float4*)shid[2][g])[cb & 7];
        float4 ta = ((const float4*)g_tw)[ca & 7];
        float4 tb = ((const float4*)g_tw)[cb & 7];
        float r = acca.x * ha.x * ta.x + acca.y * ha.y * ta.y
                + acca.z * ha.z * ta.z + acca.w * ha.w * ta.w
                + accb.x * hb.x * tb.x + accb.y * hb.y * tb.y
                + accb.z * hb.z * tb.z + accb.w * hb.w * tb.w;
        r += __shfl_xor_sync(0xffffffffu, r, 1);
        r += __shfl_xor_sync(0xffffffffu, r, 2);
        if ((c2 & 3) == 0) out[b * Esz + e] = r;
    }

    // ===== cleanup for next graph replay =====
    if (tid < TPB) { g_cnt[e0 + tid] = 0; g_hcnt[e0 + tid] = 0; }
    __syncthreads();
    if (tid == 0) {
        unsigned prev = atomicAdd(&g_fin, 1u);
        if (prev == (unsigned)gridDim.x - 1) {
            for (int i = 0; i < BMW; i++) { g_rdyA[i] = 0u; g_rdyB[i] = 0u; }
            g_front = 0u;
            g_fin = 0u;
        }
    }
}

// ---------------- launch ----------------
extern "C" void kernel_launch(void* const* d_in, const int* in_sizes, int n_in,
                              void* d_out, int out_size) {
    const float* input_x  = (const float*)d_in[0];
    const float* type_mat = (const float*)d_in[1];
    const float* e2triple = (const float*)d_in[2];
    const float* triple2e = (const float*)d_in[3];
    const float* triple2r = (const float*)d_in[4];
    const float* w        = (const float*)d_in[5];
    const float* weight   = (const float*)d_in[6];
    const float* h        = (const float*)d_in[7];
    const float* h_x      = (const float*)d_in[8];
    const float* h_type   = (const float*)d_in[9];
    const float* h_x_type = (const float*)d_in[10];
    const float* alpha    = (const float*)d_in[11];
    const float* beta     = (const float*)d_in[12];
    const float* alpha_x  = (const float*)d_in[13];
    const float* beta_x   = (const float*)d_in[14];
    float* out = (float*)d_out;

    k_setup<<<1184, 256>>>((const uint4*)e2triple, (const uint4*)triple2e,
                           (const uint4*)triple2r, input_x, type_mat,
                           alpha, beta, w, h, h_type, weight);
    k_fused<<<PGRID, 256>>>(alpha, beta, alpha_x, beta_x, h_x, h_x_type, out);
}

// round 17
// speedup vs baseline: 1.0730x; 1.0730x over previous
#include <cuda_runtime.h>
#include <math.h>

#define Bsz 8
#define Esz 2000
#define Nsz 10000
#define NRELc 25
#define Ksz 16
#define Tsz 3
#define Lsz 32
#define TAU1f 10.0f
#define BL 256
#define COL4 64
#define TPB 8
#define SLOTS 32
#define BMW 64
#define PGRID (Esz / TPB)    // 250 blocks

// ---------------- scratch ----------------
__device__ int      g_heads[Nsz];
__device__ int      g_rels[Nsz];
__device__ int      g_tailof[Nsz];
__device__ int      g_slotn[Esz * SLOTS];   // tail-keyed CSR
__device__ int      g_cnt[Esz];             // tail degree (zeroed by last block)
__device__ int      g_hslotn[Esz * SLOTS];  // head-keyed CSR
__device__ int      g_hcnt[Esz];            // head degree (zeroed by last block)
__device__ int      g_tidx[Esz];
__device__ int      g_ent[Bsz];
__device__ float    g_val[Bsz];
__device__ float    g_wp[Tsz * NRELc * Lsz];
__device__ float    g_shp[Tsz * (NRELc - 1) * Lsz];
__device__ float    g_shtp[Tsz * Ksz * Lsz];
__device__ float    g_ab[Tsz * Lsz * 2];
__device__ float    g_tw[Lsz];
__device__ float    g_sA[Esz * BL];          // sA' (hx0 factored out)
__device__ volatile unsigned g_bar;
__device__ unsigned g_fin;

__device__ __forceinline__ float clip01(float x) { return fminf(fmaxf(x, 0.0f), 1.0f); }

// ============ 1) streaming extraction + both CSRs + tables ============
__global__ void k_setup(const uint4* __restrict__ e2t,
                        const uint4* __restrict__ t2e,
                        const uint4* __restrict__ t2r,
                        const float* __restrict__ input_x,
                        const float* __restrict__ type_mat,
                        const float* __restrict__ alpha, const float* __restrict__ beta,
                        const float* __restrict__ w, const float* __restrict__ h,
                        const float* __restrict__ h_type, const float* __restrict__ weight) {
    const unsigned tid0 = threadIdx.x;
    const unsigned bi = blockIdx.x;
    const unsigned tid = bi * blockDim.x + tid0;
    const unsigned stride = gridDim.x * blockDim.x;

    // tables (param-only)
    if (bi == 0) {
        if (tid0 < Tsz * Lsz) {
            int tt = tid0 / Lsz, l = tid0 % Lsz;
            const float* wr = w + (tt * Lsz + l) * NRELc;
            float m = -1e30f;
#pragma unroll
            for (int r = 0; r < NRELc; r++) m = fmaxf(m, wr[r]);
            float s = 0.0f, ev[NRELc];
#pragma unroll
            for (int r = 0; r < NRELc; r++) { ev[r] = expf(wr[r] - m); s += ev[r]; }
            float inv = 1.0f / s;
#pragma unroll
            for (int r = 0; r < NRELc; r++)
                g_wp[(tt * NRELc + r) * Lsz + l] = ev[r] * inv;
            g_ab[(tt * Lsz + l) * 2 + 0] = clip01(alpha[tt * Lsz + l] / TAU1f);
            g_ab[(tt * Lsz + l) * 2 + 1] = clip01(beta[tt * Lsz + l] / TAU1f);
        } else if (tid0 < Tsz * Lsz + Lsz) {
            int l = tid0 - Tsz * Lsz;
            g_tw[l] = tanhf(weight[l]);
        }
    }
    if (bi >= 1 && bi < 10) {
        int i = (int)(bi - 1) * 256 + (int)tid0;
        if (i < Tsz * (NRELc - 1) * Lsz) {
            int tt = i / ((NRELc - 1) * Lsz);
            int rem = i % ((NRELc - 1) * Lsz);
            int j = rem / Lsz, l = rem % Lsz;
            g_shp[i] = clip01(h[(tt * Lsz + l) * (NRELc - 1) + j] / TAU1f);
        }
    }
    if (bi >= 10 && bi < 16) {
        int i = (int)(bi - 10) * 256 + (int)tid0;
        if (i < Tsz * Ksz * Lsz) {
            int tt = i / (Ksz * Lsz);
            int rem = i % (Ksz * Lsz);
            int k = rem / Lsz, l = rem % Lsz;
            g_shtp[i] = clip01(h_type[(tt * Lsz + l) * Ksz + k] / TAU1f);
        }
    }

    for (unsigned i = tid; i < Bsz * Esz; i += stride) {
        float v = input_x[i];
        if (v != 0.0f) { g_ent[i / Esz] = (int)(i % Esz); g_val[i / Esz] = v; }
    }
    for (unsigned i = tid; i < Esz * Ksz; i += stride)
        if (type_mat[i] != 0.0f) g_tidx[i / Ksz] = (int)(i % Ksz);

    const unsigned n3 = Nsz * NRELc / 4;
    for (unsigned i = tid; i < n3; i += stride) {
        uint4 v = __ldcs(&t2r[i]);
        if (v.x | v.y | v.z | v.w) {
            unsigned base = i * 4u;
            if (v.x) { unsigned id = base + 0; g_rels[id / NRELc] = (int)(id % NRELc); }
            if (v.y) { unsigned id = base + 1; g_rels[id / NRELc] = (int)(id % NRELc); }
            if (v.z) { unsigned id = base + 2; g_rels[id / NRELc] = (int)(id % NRELc); }
            if (v.w) { unsigned id = base + 3; g_rels[id / NRELc] = (int)(id % NRELc); }
        }
    }

    const unsigned n1 = (unsigned)Esz * Nsz / 4;   // e2triple -> heads + head CSR
    {
        unsigned i = tid;
        for (; i + 3 * stride < n1; i += 4 * stride) {
            uint4 a0 = __ldcs(&e2t[i]);
            uint4 a1 = __ldcs(&e2t[i + stride]);
            uint4 a2 = __ldcs(&e2t[i + 2 * stride]);
            uint4 a3 = __ldcs(&e2t[i + 3 * stride]);
#define PROC_H(vv, ii) \
            if ((vv).x | (vv).y | (vv).z | (vv).w) { \
                unsigned base = (ii) * 4u; \
                unsigned wsv[4] = {(vv).x, (vv).y, (vv).z, (vv).w}; \
                _Pragma("unroll") \
                for (int k = 0; k < 4; k++) if (wsv[k]) { \
                    unsigned id = base + k; \
                    unsigned n = id % Nsz; int e = (int)(id / Nsz); \
                    g_heads[n] = e; \
                    int s = atomicAdd(&g_hcnt[e], 1); \
                    if (s < SLOTS) g_hslotn[e * SLOTS + s] = (int)n; } }
            PROC_H(a0, i) PROC_H(a1, i + stride) PROC_H(a2, i + 2 * stride) PROC_H(a3, i + 3 * stride)
        }
        for (; i < n1; i += stride) { uint4 a = __ldcs(&e2t[i]); PROC_H(a, i) }
    }
    const unsigned n2 = (unsigned)Nsz * Esz / 4;   // triple2e -> tail CSR + tailof
    {
        unsigned i = tid;
        for (; i + 3 * stride < n2; i += 4 * stride) {
            uint4 a0 = __ldcs(&t2e[i]);
            uint4 a1 = __ldcs(&t2e[i + stride]);
            uint4 a2 = __ldcs(&t2e[i + 2 * stride]);
            uint4 a3 = __ldcs(&t2e[i + 3 * stride]);
#define PROC_T(vv, ii) \
            if ((vv).x | (vv).y | (vv).z | (vv).w) { \
                unsigned base = (ii) * 4u; \
                unsigned wsv[4] = {(vv).x, (vv).y, (vv).z, (vv).w}; \
                _Pragma("unroll") \
                for (int k = 0; k < 4; k++) if (wsv[k]) { \
                    unsigned id = base + k; \
                    unsigned n = id / Esz, tl = id % Esz; \
                    g_tailof[n] = (int)tl; \
                    int slot = atomicAdd(&g_cnt[tl], 1); \
                    if (slot < SLOTS) g_slotn[tl * SLOTS + slot] = (int)n; } }
            PROC_T(a0, i) PROC_T(a1, i + stride) PROC_T(a2, i + 2 * stride) PROC_T(a3, i + 3 * stride)
        }
        for (; i < n2; i += stride) { uint4 a = __ldcs(&t2e[i]); PROC_T(a, i) }
    }
}

// ============ 2) fused kernel: ONE grid barrier ============
__global__ void __launch_bounds__(256, 2)
k_fused(const float* __restrict__ alpha_x, const float* __restrict__ beta_x,
        const float* __restrict__ h_x, const float* __restrict__ h_x_type,
        float* __restrict__ out) {
    const int tid = threadIdx.x;
    const int bi = blockIdx.x;
    const int g = tid >> 5;          // own row 0..7 (warp per row)
    const int c2 = tid & 31;         // lane: owns float4 slots {2c2, 2c2+1}
    const int ca = 2 * c2, cb = 2 * c2 + 1;
    const int b = c2 >> 2;
    const int e0 = bi * TPB;
    const int e  = e0 + g;

    __shared__ unsigned strip[TPB][SLOTS];
    __shared__ float    shid0[TPB][Lsz], shid2[TPB][Lsz];
    __shared__ float    shx0[BL];
    __shared__ float    shxacc[Bsz * NRELc];
    __shared__ unsigned smaskl[TPB];
    __shared__ int      scnt[TPB];
    __shared__ int      sent[Bsz];
    __shared__ float    sval[Bsz];
    __shared__ unsigned sbm0[BMW], sbm1[BMW];
    __shared__ int      slist[256];
    __shared__ int      slcnt;
    __shared__ int      slast;

    if (tid < TPB) { smaskl[tid] = 0u; scnt[tid] = min(g_cnt[e0 + tid], SLOTS); }
    if (tid >= 32 && tid < 32 + BMW) { sbm0[tid - 32] = 0u; sbm1[tid - 32] = 0u; }
    if (tid >= 96 && tid < 96 + Bsz * NRELc) shxacc[tid - 96] = 0.0f;
    if (tid >= 8 && tid < 8 + Bsz) { sent[tid - 8] = g_ent[tid - 8]; sval[tid - 8] = g_val[tid - 8]; }
    if (tid == 0) slcnt = 0;
    __syncthreads();

    // ---- own strips + masks; frontier hop 1 (every block, redundant) ----
    if (c2 < scnt[g]) {
        int n = g_slotn[e * SLOTS + c2];
        int hd = g_heads[n], r = g_rels[n];
        strip[g][c2] = (unsigned)hd | ((unsigned)r << 11);
        if (r < NRELc - 1) atomicOr(&smaskl[g], 1u << r);
    }
    {
        int b2 = g, slot = c2;
        int entb = sent[b2];
        int hc = min(g_hcnt[entb], SLOTS);
        if (slot < hc) {
            int n = g_hslotn[entb * SLOTS + slot];
            int tl = g_tailof[n], r = g_rels[n];
            atomicOr(&sbm0[tl >> 5], 1u << (tl & 31));
            atomicAdd(&shxacc[b2 * NRELc + r], sval[b2]);
        }
    }
    __syncthreads();

    // ---- list0 + shid0/shid2 ----
    for (int i = tid; i < Esz; i += 256)
        if ((sbm0[i >> 5] >> (i & 31)) & 1u) { int p = atomicAdd(&slcnt, 1); slist[p] = i; }
    {
        int row = g, l = c2;
        int ti = g_tidx[e];
        unsigned mrow = smaskl[row];
        {
            float a  = g_ab[(0 * Lsz + l) * 2 + 0];
            float bb = g_ab[(0 * Lsz + l) * 2 + 1];
            float s1 = g_shtp[(0 * Ksz + ti) * Lsz + l];
            float s2 = 0.0f; unsigned m = mrow;
            while (m) { int jj = __ffs(m) - 1; s2 += g_shp[(0 * (NRELc - 1) + jj) * Lsz + l]; m &= m - 1; }
            shid0[row][l] = clip01(a * s1 + bb * s2) + (1.0f - clip01(a + bb));
        }
        {
            float a  = g_ab[(2 * Lsz + l) * 2 + 0];
            float bb = g_ab[(2 * Lsz + l) * 2 + 1];
            float s1 = g_shtp[(2 * Ksz + ti) * Lsz + l];
            float s2 = 0.0f; unsigned m = mrow;
            while (m) { int jj = __ffs(m) - 1; s2 += g_shp[(2 * (NRELc - 1) + jj) * Lsz + l]; m &= m - 1; }
            shid2[row][l] = clip01(a * s1 + bb * s2) + (1.0f - clip01(a + bb));
        }
    }
    __syncthreads();

    // ---- hop 2 (bm1) + hx0 ----
    {
        int tot = slcnt * SLOTS;
        for (int i = tid; i < tot; i += 256) {
            int row = slist[i >> 5], slot = i & 31;
            int hc = min(g_hcnt[row], SLOTS);
            if (slot < hc) {
                int n = g_hslotn[row * SLOTS + slot];
                int tl = g_tailof[n];
                atomicOr(&sbm1[tl >> 5], 1u << (tl & 31));
            }
        }
    }
    {
        int b2 = tid >> 5, l = tid & 31;
        int entb = sent[b2]; float valb = sval[b2];
        float a  = g_ab[(0 * Lsz + l) * 2 + 0];
        float bb = g_ab[(0 * Lsz + l) * 2 + 1];
        float gate = 1.0f - clip01(clip01(alpha_x[l] / TAU1f) + clip01(beta_x[l] / TAU1f));
        float htx = clip01(h_x_type[l * Ksz + g_tidx[entb]] / TAU1f) * valb;
        float hxl = 0.0f;
#pragma unroll
        for (int j = 0; j < NRELc - 1; j++) {
            int col = (j < 12) ? (12 + j) : (j - 12);
            hxl += clip01(shxacc[b2 * NRELc + col]) * clip01(h_x[l * (NRELc - 1) + j] / TAU1f);
        }
        shx0[tid] = clip01(a * htx + bb * hxl) + gate;
    }
    __syncthreads();

    const float4* wp4 = (const float4*)g_wp;
    const int cnt = scnt[g];

    // ---- phase 0: input -> sA'  (hx0 factored out; rows in bm0 only) ----
    if ((sbm0[e >> 5] >> (e & 31)) & 1u) {
        int sentb = sent[b]; float svalb = sval[b];
        float4 acca = make_float4(0.f, 0.f, 0.f, 0.f);
        float4 accb = make_float4(0.f, 0.f, 0.f, 0.f);
        for (int j = 0; j < cnt; j++) {
            unsigned u = strip[g][j];
            if ((int)(u & 0x7ffu) == sentb) {
                unsigned rbase = (0 * NRELc + (u >> 11)) * 8;
                float4 wa = __ldg(&wp4[rbase + (ca & 7)]);
                float4 wb = __ldg(&wp4[rbase + (cb & 7)]);
                acca.x = fmaf(svalb, wa.x, acca.x); acca.y = fmaf(svalb, wa.y, acca.y);
                acca.z = fmaf(svalb, wa.z, acca.z); acca.w = fmaf(svalb, wa.w, acca.w);
                accb.x = fmaf(svalb, wb.x, accb.x); accb.y = fmaf(svalb, wb.y, accb.y);
                accb.z = fmaf(svalb, wb.z, accb.z); accb.w = fmaf(svalb, wb.w, accb.w);
            }
        }
        float4 ha = ((const float4*)shid0[g])[ca & 7];
        float4 hb = ((const float4*)shid0[g])[cb & 7];
        ((float4*)g_sA)[e * COL4 + ca] = make_float4(
            acca.x * ha.x, acca.y * ha.y, acca.z * ha.z, acca.w * ha.w);
        ((float4*)g_sA)[e * COL4 + cb] = make_float4(
            accb.x * hb.x, accb.y * hb.y, accb.z * hb.z, accb.w * hb.w);
    }

    // ---- THE single grid barrier (sA' visibility) ----
    __syncthreads();
    if (tid == 0) {
        __threadfence();
        atomicAdd((unsigned*)&g_bar, 1u);
        while (g_bar < (unsigned)PGRID) { __nanosleep(32); }
    }
    __syncthreads();
    __threadfence();

    // ---- phase 1+2 fused: recompute sB' rows on demand, accumulate out ----
    {
        float4 acc2a = make_float4(0.f, 0.f, 0.f, 0.f);
        float4 acc2b = make_float4(0.f, 0.f, 0.f, 0.f);
        bool pass = false;
        unsigned myu = 0;
        if (c2 < cnt) {
            myu = strip[g][c2];
            unsigned hh = myu & 0x7ffu;
            pass = (sbm1[hh >> 5] >> (hh & 31)) & 1u;
        }
        unsigned pm = __ballot_sync(0xffffffffu, pass);
        while (pm) {
            int j = __ffs(pm) - 1; pm &= pm - 1;
            unsigned u = __shfl_sync(0xffffffffu, myu, j);
            unsigned hrow = u & 0x7ffu;
            unsigned rj = u >> 11;
            // lane-parallel load of hrow's trips
            int ch = min(g_cnt[hrow], SLOTS);
            int nn = (c2 < ch) ? g_slotn[hrow * SLOTS + c2] : -1;
            unsigned hdk = 0, rk = 0; bool vld = (nn >= 0);
            if (vld) { hdk = (unsigned)g_heads[nn]; rk = (unsigned)g_rels[nn]; }
            // mask for hid1 of hrow
            unsigned mk = (vld && rk < NRELc - 1) ? (1u << rk) : 0u;
#pragma unroll
            for (int off = 16; off > 0; off >>= 1)
                mk |= __shfl_xor_sync(0xffffffffu, mk, off);
            // hid1 at l = lane
            float hidl;
            {
                int l = c2;
                float a  = g_ab[(1 * Lsz + l) * 2 + 0];
                float bb = g_ab[(1 * Lsz + l) * 2 + 1];
                float s1 = g_shtp[(1 * Ksz + g_tidx[hrow]) * Lsz + l];
                float s2 = 0.0f; unsigned m = mk;
                while (m) { int jj = __ffs(m) - 1; s2 += g_shp[(1 * (NRELc - 1) + jj) * Lsz + l]; m &= m - 1; }
                hidl = clip01(a * s1 + bb * s2) + (1.0f - clip01(a + bb));
            }
            // sB' pre-hid accumulation over hrow's bm0 trips
            float4 a1a = make_float4(0.f, 0.f, 0.f, 0.f);
            float4 a1b = make_float4(0.f, 0.f, 0.f, 0.f);
            unsigned km = __ballot_sync(0xffffffffu,
                vld && ((sbm0[hdk >> 5] >> (hdk & 31)) & 1u));
            while (km) {
                int k = __ffs(km) - 1; km &= km - 1;
                unsigned hb2 = __shfl_sync(0xffffffffu, hdk, k);
                unsigned rb2 = __shfl_sync(0xffffffffu, rk, k);
                float4 va = ((const float4*)g_sA)[hb2 * COL4 + ca];
                float4 vb = ((const float4*)g_sA)[hb2 * COL4 + cb];
                unsigned rbase = (1 * NRELc + rb2) * 8;
                float4 wa = __ldg(&wp4[rbase + (ca & 7)]);
                float4 wb = __ldg(&wp4[rbase + (cb & 7)]);
                a1a.x = fmaf(va.x, wa.x, a1a.x); a1a.y = fmaf(va.y, wa.y, a1a.y);
                a1a.z = fmaf(va.z, wa.z, a1a.z); a1a.w = fmaf(va.w, wa.w, a1a.w);
                a1b.x = fmaf(vb.x, wb.x, a1b.x); a1b.y = fmaf(vb.y, wb.y, a1b.y);
                a1b.z = fmaf(vb.z, wb.z, a1b.z); a1b.w = fmaf(vb.w, wb.w, a1b.w);
            }
            // gather hid1 at this thread's 8 l's
            int la0 = (ca & 7) * 4;
            float h0 = __shfl_sync(0xffffffffu, hidl, la0 + 0);
            float h1 = __shfl_sync(0xffffffffu, hidl, la0 + 1);
            float h2 = __shfl_sync(0xffffffffu, hidl, la0 + 2);
            float h3 = __shfl_sync(0xffffffffu, hidl, la0 + 3);
            float h4 = __shfl_sync(0xffffffffu, hidl, la0 + 4);
            float h5 = __shfl_sync(0xffffffffu, hidl, la0 + 5);
            float h6 = __shfl_sync(0xffffffffu, hidl, la0 + 6);
            float h7 = __shfl_sync(0xffffffffu, hidl, la0 + 7);
            unsigned r2base = (2 * NRELc + rj) * 8;
            float4 wja = __ldg(&wp4[r2base + (ca & 7)]);
            float4 wjb = __ldg(&wp4[r2base + (cb & 7)]);
            acc2a.x = fmaf(wja.x, a1a.x * h0, acc2a.x);
            acc2a.y = fmaf(wja.y, a1a.y * h1, acc2a.y);
            acc2a.z = fmaf(wja.z, a1a.z * h2, acc2a.z);
            acc2a.w = fmaf(wja.w, a1a.w * h3, acc2a.w);
            acc2b.x = fmaf(wjb.x, a1b.x * h4, acc2b.x);
            acc2b.y = fmaf(wjb.y, a1b.y * h5, acc2b.y);
            acc2b.z = fmaf(wjb.z, a1b.z * h6, acc2b.z);
            acc2b.w = fmaf(wjb.w, a1b.w * h7, acc2b.w);
        }
        // final: apply hid2, hx0, tanh(weight); reduce over 32 l's (4 lanes per b)
        float4 ha = ((const float4*)shid2[g])[ca & 7];
        float4 hb = ((const float4*)shid2[g])[cb & 7];
        float4 xa = ((const float4*)shx0)[ca];
        float4 xb = ((const float4*)shx0)[cb];
        float4 ta = ((const float4*)g_tw)[ca & 7];
        float4 tb = ((const float4*)g_tw)[cb & 7];
        float r = acc2a.x * ha.x * xa.x * ta.x + acc2a.y * ha.y * xa.y * ta.y
                + acc2a.z * ha.z * xa.z * ta.z + acc2a.w * ha.w * xa.w * ta.w
                + acc2b.x * hb.x * xb.x * tb.x + acc2b.y * hb.y * xb.y * tb.y
                + acc2b.z * hb.z * xb.z * tb.z + acc2b.w * hb.w * xb.w * tb.w;
        r += __shfl_xor_sync(0xffffffffu, r, 1);
        r += __shfl_xor_sync(0xffffffffu, r, 2);
        if ((c2 & 3) == 0) out[b * Esz + e] = r;
    }

    // ---- cleanup by the LAST finishing block (safe: all reads done) ----
    __syncthreads();
    if (tid == 0) {
        unsigned prev = atomicAdd(&g_fin, 1u);
        slast = (prev == (unsigned)gridDim.x - 1) ? 1 : 0;
    }
    __syncthreads();
    if (slast) {
        for (int i = tid; i < Esz; i += 256) { g_cnt[i] = 0; g_hcnt[i] = 0; }
        if (tid == 0) { g_bar = 0u; g_fin = 0u; }
    }
}

// ---------------- launch ----------------
extern "C" void kernel_launch(void* const* d_in, const int* in_sizes, int n_in,
                              void* d_out, int out_size) {
    const float* input_x  = (const float*)d_in[0];
    const float* type_mat = (const float*)d_in[1];
    const float* e2triple = (const float*)d_in[2];
    const float* triple2e = (const float*)d_in[3];
    const float* triple2r = (const float*)d_in[4];
    const float* w        = (const float*)d_in[5];
    const float* weight   = (const float*)d_in[6];
    const float* h        = (const float*)d_in[7];
    const float* h_x      = (const float*)d_in[8];
    const float* h_type   = (const float*)d_in[9];
    const float* h_x_type = (const float*)d_in[10];
    const float* alpha    = (const float*)d_in[11];
    const float* beta     = (const float*)d_in[12];
    const float* alpha_x  = (const float*)d_in[13];
    const float* beta_x   = (const float*)d_in[14];
    float* out = (float*)d_out;

    k_setup<<<1184, 256>>>((const uint4*)e2triple, (const uint4*)triple2e,
                           (const uint4*)triple2r, input_x, type_mat,
                           alpha, beta, w, h, h_type, weight);
    k_fused<<<PGRID, 256>>>(alpha_x, beta_x, h_x, h_x_type, out);
}